// round 8
// baseline (speedup 1.0000x reference)
#include <cuda_runtime.h>
#include <cstdint>

// Problem constants: N_UNIQUE=10000, N_BASES=10, FILTERS=16, B=32, L=100000
#define N_UNIQUE 10000
#define N_BASES  10
#define FILTERS  16
#define N_ELEMS  (32 * 100000)           // 3,200,000
#define N_OUT4   (N_ELEMS * 4)           // 12,800,000 float4 outputs
#define TPB      256
#define VEC      4                        // float4 per thread per iteration
#define CHUNK4   (TPB * VEC)              // 1024 float4 = 16KB per iteration
#define ITERS    4                        // iterations per block
// 12,800,000 / (1024*4) = 3125 blocks exactly — no tail.
#define GATHER_BLOCKS (N_OUT4 / (CHUNK4 * ITERS))

// Precomputed bias-fused unique-value table, fp32 (device global scratch).
__device__ float4 g_shrunk4[N_UNIQUE * 4];   // [n_unique][16 floats]

// Kernel 1: shrunk_biased[u][f] = sum_b X_spline[u][b]*kernel[b][f] + bias[f]
__global__ void precompute_shrunk(const float* __restrict__ X_spline,
                                  const float* __restrict__ kern,
                                  const float* __restrict__ bias) {
    int t = blockIdx.x * blockDim.x + threadIdx.x;
    if (t >= N_UNIQUE * FILTERS) return;
    int u = t >> 4;
    int f = t & 15;
    float acc = __ldg(bias + f);
#pragma unroll
    for (int b = 0; b < N_BASES; ++b)
        acc = fmaf(__ldg(X_spline + u * N_BASES + b), __ldg(kern + b * FILTERS + f), acc);
    reinterpret_cast<float*>(g_shrunk4)[t] = acc;
}

static __device__ __forceinline__ uint32_t smem_addr_u32(const void* p) {
    uint32_t a;
    asm("{ .reg .u64 t; cvta.to.shared.u64 t, %1; cvt.u32.u64 %0, t; }"
        : "=r"(a) : "l"(p));
    return a;
}

// Kernel 2: gather into SMEM, stream to GMEM via async bulk copies (TMA).
// Thread mapping per iteration identical to R2: float4 slot i -> element
// e=i>>2, quarter j=i&3 (j == tid&3, constant per thread).
__global__ __launch_bounds__(TPB) void gather_out(const int* __restrict__ idx,
                                                  float4* __restrict__ out4) {
    __shared__ float4 buf[2][CHUNK4];     // 2 x 16KB double buffer
    const unsigned tid = threadIdx.x;

#pragma unroll
    for (int iter = 0; iter < ITERS; ++iter) {
        const int b = iter & 1;
        const unsigned gbase = blockIdx.x * (CHUNK4 * ITERS) + iter * CHUNK4 + tid;

        // Buffer reuse guard: the bulk store issued 2 iterations ago must
        // have finished READING this buffer.
        if (iter >= 2) {
            if (tid == 0)
                asm volatile("cp.async.bulk.wait_group.read 1;" ::: "memory");
            __syncthreads();
        }

        // Phase 1: independent idx loads (streamed).
        int u[VEC];
#pragma unroll
        for (int k = 0; k < VEC; ++k)
            u[k] = __ldcs(idx + ((gbase + k * TPB) >> 2));

        // Phase 2: independent table gathers (L2-resident).
        float4 v[VEC];
#pragma unroll
        for (int k = 0; k < VEC; ++k)
            v[k] = __ldg(&g_shrunk4[(unsigned)u[k] * 4u + (tid & 3u)]);

        // Phase 3: conflict-free STS.128 into the staging buffer.
#pragma unroll
        for (int k = 0; k < VEC; ++k)
            buf[b][tid + k * TPB] = v[k];

        __syncthreads();                  // buffer fully written

        // One thread launches the async 16KB bulk store for this chunk.
        if (tid == 0) {
            asm volatile("fence.proxy.async.shared::cta;" ::: "memory");
            const float4* gdst = out4 + (blockIdx.x * (CHUNK4 * ITERS) + iter * CHUNK4);
            uint32_t saddr = smem_addr_u32(&buf[b][0]);
            asm volatile(
                "cp.async.bulk.global.shared::cta.bulk_group [%0], [%1], %2;"
                :: "l"(gdst), "r"(saddr), "r"((int)(CHUNK4 * sizeof(float4)))
                : "memory");
            asm volatile("cp.async.bulk.commit_group;" ::: "memory");
        }
    }

    // Drain all outstanding bulk stores before kernel exit.
    if (tid == 0)
        asm volatile("cp.async.bulk.wait_group 0;" ::: "memory");
}

extern "C" void kernel_launch(void* const* d_in, const int* in_sizes, int n_in,
                              void* d_out, int out_size) {
    // Identify inputs by element count (all distinct):
    // idx: 3,200,000 | X_spline: 100,000 | kernel: 160 | bias: 16
    const int*   idx      = nullptr;
    const float* X_spline = nullptr;
    const float* kern     = nullptr;
    const float* bias     = nullptr;
    for (int i = 0; i < n_in; ++i) {
        switch (in_sizes[i]) {
            case N_ELEMS:             idx      = (const int*)  d_in[i]; break;
            case N_UNIQUE * N_BASES:  X_spline = (const float*)d_in[i]; break;
            case N_BASES * FILTERS:   kern     = (const float*)d_in[i]; break;
            case FILTERS:             bias     = (const float*)d_in[i]; break;
            default: break;
        }
    }

    {
        int total = N_UNIQUE * FILTERS;
        precompute_shrunk<<<(total + TPB - 1) / TPB, TPB>>>(X_spline, kern, bias);
    }
    gather_out<<<GATHER_BLOCKS, TPB>>>(idx, (float4*)d_out);
}